// round 13
// baseline (speedup 1.0000x reference)
#include <cuda_runtime.h>
#include <math.h>

#define N_NODES 6144
#define N_EDGES 196608
#define IN_F    256
#define OUT_F   128
#define EDGE_D  16
#define ALPHA   0.2f
#define CAP     128          // per-row bucket capacity (Poisson(32) tail @128 ~ e^-85)

#define BM 16
#define GEMM_BLOCKS (N_NODES / BM)      // 384
#define INIT_BLOCKS 24                  // 24 * 256 = 6144
#define K1_BLOCKS   (GEMM_BLOCKS + INIT_BLOCKS)

// ---------------- scratch (static device globals; no allocation allowed) ----
__device__ float g_h[N_NODES * OUT_F];       // transformed features
__device__ float g_s1[N_NODES];
__device__ float g_s2[N_NODES];
__device__ int   g_off[N_NODES];             // per-row fill count
__device__ int   g_bdst[N_NODES * CAP];      // bucket: dst node
__device__ int   g_beid[N_NODES * CAP];      // bucket: edge id (dedup tie-break)
__device__ float g_bes [N_NODES * CAP];      // bucket: edge score
__device__ int   g_is64 = 1;                 // dtype flag: only ever cleared

__device__ __forceinline__ int load_idx(const void* ei_raw, int row, int e, int is64) {
    int v;
    if (is64) v = (int)((const long long*)ei_raw)[(long long)row * N_EDGES + e];
    else      v = ((const int*)ei_raw)[row * N_EDGES + e];
    v = v < 0 ? 0 : (v >= N_NODES ? N_NODES - 1 : v);   // never form a wild address
    return v;
}

// ---------------- kernel 1: SGEMM (+s1/s2 epilogue) | init tail blocks ------
// BM=16 x BN=128, BK=32, 256 threads, each thread 2x4. 384 gemm blocks ->
// the whole launch is resident in one wave (4 blocks/SM, 32 warps/SM).
__global__ __launch_bounds__(256) void gemm_init_kernel(const float* __restrict__ A,
                                                        const float* __restrict__ B,
                                                        const float* __restrict__ a,
                                                        const void* __restrict__ ei_raw) {
    if (blockIdx.x >= GEMM_BLOCKS) {
        int i = (blockIdx.x - GEMM_BLOCKS) * 256 + threadIdx.x;   // 0..6143
        g_off[i] = 0;
        long long v = ((const long long*)ei_raw)[i];
        if (v < 0 || v >= N_NODES) g_is64 = 0;   // benign: only ever cleared
        return;
    }

    __shared__ float  As[32][17];     // [k][m], padded
    __shared__ float4 Bs[32][32];     // [k][col4]

    int tid = threadIdx.x;
    int ty  = tid >> 5;               // 0..7  -> rows ty*2, ty*2+1
    int tx  = tid & 31;               // 0..31 -> cols tx*4 .. tx*4+3
    int blockRow = blockIdx.x * BM;

    int arow = tid >> 3;              // 0..15 (threads 0..127)
    int ak4  = (tid & 7) * 4;         // 0,4,...,28

    float acc[2][4] = {};

    for (int k0 = 0; k0 < IN_F; k0 += 32) {
        if (tid < 128) {
            float4 av = *(const float4*)&A[(blockRow + arow) * IN_F + k0 + ak4];
            As[ak4 + 0][arow] = av.x;
            As[ak4 + 1][arow] = av.y;
            As[ak4 + 2][arow] = av.z;
            As[ak4 + 3][arow] = av.w;
        }
#pragma unroll
        for (int r = 0; r < 4; r++) {
            int idx = tid + r * 256;          // 0..1023
            int kb  = idx >> 5;               // 0..31
            int cb  = idx & 31;               // 0..31
            Bs[kb][cb] = *(const float4*)&B[(k0 + kb) * OUT_F + cb * 4];
        }
        __syncthreads();
#pragma unroll
        for (int k = 0; k < 32; k++) {
            float a0 = As[k][ty * 2 + 0];
            float a1 = As[k][ty * 2 + 1];
            float4 bv = Bs[k][tx];
            acc[0][0] += a0 * bv.x; acc[0][1] += a0 * bv.y; acc[0][2] += a0 * bv.z; acc[0][3] += a0 * bv.w;
            acc[1][0] += a1 * bv.x; acc[1][1] += a1 * bv.y; acc[1][2] += a1 * bv.z; acc[1][3] += a1 * bv.w;
        }
        __syncthreads();
    }

#pragma unroll
    for (int r = 0; r < 2; r++) {
        float4 v = make_float4(acc[r][0], acc[r][1], acc[r][2], acc[r][3]);
        *(float4*)&g_h[(blockRow + ty * 2 + r) * OUT_F + tx * 4] = v;
    }

    float4 a1v = *(const float4*)&a[tx * 4];
    float4 a2v = *(const float4*)&a[OUT_F + tx * 4];
#pragma unroll
    for (int r = 0; r < 2; r++) {
        float p1 = acc[r][0] * a1v.x + acc[r][1] * a1v.y + acc[r][2] * a1v.z + acc[r][3] * a1v.w;
        float p2 = acc[r][0] * a2v.x + acc[r][1] * a2v.y + acc[r][2] * a2v.z + acc[r][3] * a2v.w;
#pragma unroll
        for (int o = 16; o > 0; o >>= 1) {
            p1 += __shfl_xor_sync(0xffffffffu, p1, o);
            p2 += __shfl_xor_sync(0xffffffffu, p2, o);
        }
        if (tx == 0) {
            int row = blockRow + ty * 2 + r;
            g_s1[row] = p1;
            g_s2[row] = p2;
        }
    }
}

// ---------------- fused edge pass: es + direct bucket scatter ---------------
#define E_PER 4
__global__ __launch_bounds__(256) void edge_kernel(const float* __restrict__ ef,
                                                   const float* __restrict__ a,
                                                   const void* __restrict__ ei) {
    int t = blockIdx.x * blockDim.x + threadIdx.x;
    int base = t * E_PER;
    if (base >= N_EDGES) return;
    int is64 = g_is64;

    const float* a3 = a + 2 * OUT_F;
    float4 av0 = *(const float4*)&a3[0];
    float4 av1 = *(const float4*)&a3[4];
    float4 av2 = *(const float4*)&a3[8];
    float4 av3 = *(const float4*)&a3[12];

    float4 fv[E_PER][4];
#pragma unroll
    for (int j = 0; j < E_PER; j++) {
#pragma unroll
        for (int q = 0; q < 4; q++)
            fv[j][q] = *(const float4*)&ef[(base + j) * EDGE_D + q * 4];
    }
    int src[E_PER], dst[E_PER];
#pragma unroll
    for (int j = 0; j < E_PER; j++) {
        src[j] = load_idx(ei, 0, base + j, is64);
        dst[j] = load_idx(ei, 1, base + j, is64);
    }
#pragma unroll
    for (int j = 0; j < E_PER; j++) {
        float s = fv[j][0].x * av0.x + fv[j][0].y * av0.y + fv[j][0].z * av0.z + fv[j][0].w * av0.w
                + fv[j][1].x * av1.x + fv[j][1].y * av1.y + fv[j][1].z * av1.z + fv[j][1].w * av1.w
                + fv[j][2].x * av2.x + fv[j][2].y * av2.y + fv[j][2].z * av2.z + fv[j][2].w * av2.w
                + fv[j][3].x * av3.x + fv[j][3].y * av3.y + fv[j][3].z * av3.z + fv[j][3].w * av3.w;
        int pos = atomicAdd(&g_off[src[j]], 1);
        if (pos < CAP) {
            int slot = src[j] * CAP + pos;
            g_bdst[slot] = dst[j];
            g_beid[slot] = base + j;
            g_bes [slot] = s;
        }
    }
}

// ---------------- attention (block per row, measured best structure) --------
__global__ __launch_bounds__(128) void attn_kernel(float* __restrict__ out) {
    __shared__ int    sdst[CAP];
    __shared__ int    seid[CAP];
    __shared__ float  sw[CAP];
    __shared__ float  sinvz;
    __shared__ float4 racc[4][32];

    int i = blockIdx.x;
    int t = threadIdx.x;
    int g = t >> 5;                   // warp / edge-group
    int l = t & 31;                   // lane / feature chunk
    int d = g_off[i];
    if (d > CAP) d = CAP;

    if (d == 0) {                     // all-masked row -> uniform softmax = column mean
        float s = 0.f;
        for (int n = 0; n < N_NODES; n++) s += g_h[n * OUT_F + t];
        out[i * OUT_F + t] = s / (float)N_NODES;
        return;
    }

    float s1i = g_s1[i];
    if (t < d) {
        int slot = i * CAP + t;
        sdst[t] = g_bdst[slot];
        seid[t] = g_beid[slot];
        sw[t]   = g_bes [slot];
    }
    __syncthreads();

    if (t < d) {
        int dst = sdst[t];
        int eid = seid[t];
        // dedup duplicate (src,dst): last-written (max eid) edge wins.
        bool win = true;
        for (int k = 0; k < d; k++)
            if (sdst[k] == dst && seid[k] > eid) win = false;
        float e = -1e30f;
        if (win) {
            e = s1i + g_s2[dst] + sw[t];
            e = (e > 0.f) ? e : ALPHA * e;
        }
        sw[t] = e;
    }
    __syncthreads();

    // warp 0: row softmax (max, exp, sum) over d entries
    if (g == 0) {
        float v[4];
        float m = -1e30f;
#pragma unroll
        for (int j = 0; j < 4; j++) {
            int k = l + 32 * j;
            v[j] = (k < d) ? sw[k] : -1e30f;
            m = fmaxf(m, v[j]);
        }
#pragma unroll
        for (int o = 16; o > 0; o >>= 1) m = fmaxf(m, __shfl_xor_sync(0xffffffffu, m, o));
        float z = 0.f;
#pragma unroll
        for (int j = 0; j < 4; j++) {
            int k = l + 32 * j;
            if (k < d) {
                float w = __expf(v[j] - m);
                sw[k] = w;
                z += w;
            }
        }
#pragma unroll
        for (int o = 16; o > 0; o >>= 1) z += __shfl_xor_sync(0xffffffffu, z, o);
        if (l == 0) sinvz = 1.f / z;
    }
    __syncthreads();

    // gather: warp g handles edges g, g+4, ...; float4 per lane
    const float4* h4 = (const float4*)g_h;
    float4 acc = make_float4(0.f, 0.f, 0.f, 0.f);
    for (int k = g; k < d; k += 4) {
        float  wk  = sw[k];
        int    dst = sdst[k];
        float4 hv  = h4[dst * 32 + l];
        acc.x += wk * hv.x; acc.y += wk * hv.y; acc.z += wk * hv.z; acc.w += wk * hv.w;
    }
    racc[g][l] = acc;
    __syncthreads();

    if (g == 0) {
        float4 a0 = racc[0][l], a1 = racc[1][l], a2 = racc[2][l], a3 = racc[3][l];
        float invz = sinvz;
        float4 o;
        o.x = (a0.x + a1.x + a2.x + a3.x) * invz;
        o.y = (a0.y + a1.y + a2.y + a3.y) * invz;
        o.z = (a0.z + a1.z + a2.z + a3.z) * invz;
        o.w = (a0.w + a1.w + a2.w + a3.w) * invz;
        ((float4*)out)[i * 32 + l] = o;
    }
}

// ---------------- launch ----------------------------------------------------
extern "C" void kernel_launch(void* const* d_in, const int* in_sizes, int n_in,
                              void* d_out, int out_size) {
    const float* input_h       = (const float*)d_in[0];
    const void*  edge_index    = (const void*)d_in[1];
    const float* edge_features = (const float*)d_in[2];
    const float* W             = (const float*)d_in[3];
    const float* a             = (const float*)d_in[4];
    float* out = (float*)d_out;

    gemm_init_kernel<<<K1_BLOCKS, 256>>>(input_h, W, a, edge_index);
    edge_kernel<<<N_EDGES / (256 * E_PER), 256>>>(edge_features, a, edge_index);
    attn_kernel<<<N_NODES, 128>>>(out);
}

// round 14
// speedup vs baseline: 1.0558x; 1.0558x over previous
#include <cuda_runtime.h>
#include <math.h>

#define N_NODES 6144
#define N_EDGES 196608
#define IN_F    256
#define OUT_F   128
#define EDGE_D  16
#define ALPHA   0.2f
#define CAP     128          // per-row bucket capacity (Poisson(32) tail @128 ~ e^-85)

#define GEMM_BLOCKS (N_NODES / 32)      // 192
#define INIT_BLOCKS 24                  // 24 * 256 = 6144
#define K1_BLOCKS   (GEMM_BLOCKS + INIT_BLOCKS)

// ---------------- scratch (static device globals; no allocation allowed) ----
__device__ float g_h[N_NODES * OUT_F];       // transformed features
__device__ float g_s1[N_NODES];
__device__ float g_s2[N_NODES];
__device__ int   g_off[N_NODES];             // per-row fill count
__device__ int   g_bdst[N_NODES * CAP];      // bucket: dst node
__device__ int   g_beid[N_NODES * CAP];      // bucket: edge id (dedup tie-break)
__device__ float g_bes [N_NODES * CAP];      // bucket: edge score
__device__ int   g_is64 = 1;                 // dtype flag: only ever cleared

__device__ __forceinline__ int load_idx(const void* ei_raw, int row, int e, int is64) {
    int v;
    if (is64) v = (int)((const long long*)ei_raw)[(long long)row * N_EDGES + e];
    else      v = ((const int*)ei_raw)[row * N_EDGES + e];
    v = v < 0 ? 0 : (v >= N_NODES ? N_NODES - 1 : v);   // never form a wild address
    return v;
}

// ---------------- packed f32x2 helpers (sm_103a FFMA2) ----------------------
__device__ __forceinline__ unsigned long long pack2(float x) {
    unsigned long long r;
    asm("mov.b64 %0, {%1, %1};" : "=l"(r) : "f"(x));
    return r;
}
__device__ __forceinline__ float2 unpack2(unsigned long long v) {
    float lo, hi;
    asm("mov.b64 {%0, %1}, %2;" : "=f"(lo), "=f"(hi) : "l"(v));
    return make_float2(lo, hi);
}
#define FMA2(d, a, b) asm("fma.rn.f32x2 %0, %1, %2, %0;" : "+l"(d) : "l"(a), "l"(b))

// ---------------- kernel 1: SGEMM (+s1/s2 epilogue) | init tail blocks ------
// BM=32 x BN=128, BK=32, 256 threads, each thread 4 rows x 4 cols, computed as
// 8 packed f32x2 accumulators. A values pre-packed {v,v} in smem (LDS.64
// broadcast); B pairs read as ulonglong2 from the float4 tile.
__global__ __launch_bounds__(256) void gemm_init_kernel(const float* __restrict__ A,
                                                        const float* __restrict__ B,
                                                        const float* __restrict__ a,
                                                        const void* __restrict__ ei_raw) {
    if (blockIdx.x >= GEMM_BLOCKS) {
        int i = (blockIdx.x - GEMM_BLOCKS) * 256 + threadIdx.x;   // 0..6143
        g_off[i] = 0;
        long long v = ((const long long*)ei_raw)[i];
        if (v < 0 || v >= N_NODES) g_is64 = 0;   // benign: only ever cleared
        return;
    }

    __shared__ unsigned long long As2[32][33];   // [k][m], value pre-packed {v,v}
    __shared__ float4 Bs[32][32];                // [k][col4]

    int tid = threadIdx.x;
    int ty  = tid >> 5;               // 0..7  -> rows ty*4 .. ty*4+3
    int tx  = tid & 31;               // 0..31 -> cols tx*4 .. tx*4+3
    int blockRow = blockIdx.x * 32;

    int arow = tid >> 3;              // 0..31
    int ak4  = (tid & 7) * 4;         // 0,4,...,28

    unsigned long long acc2[4][2] = {};   // [row][pair]; pair0 = cols {0,1}, pair1 = {2,3}

    for (int k0 = 0; k0 < IN_F; k0 += 32) {
        float4 av = *(const float4*)&A[(blockRow + arow) * IN_F + k0 + ak4];
        As2[ak4 + 0][arow] = pack2(av.x);
        As2[ak4 + 1][arow] = pack2(av.y);
        As2[ak4 + 2][arow] = pack2(av.z);
        As2[ak4 + 3][arow] = pack2(av.w);
#pragma unroll
        for (int r = 0; r < 4; r++) {
            int idx = tid + r * 256;          // 0..1023
            int kb  = idx >> 5;               // 0..31
            int cb  = idx & 31;               // 0..31
            Bs[kb][cb] = *(const float4*)&B[(k0 + kb) * OUT_F + cb * 4];
        }
        __syncthreads();
#pragma unroll
        for (int k = 0; k < 32; k++) {
            unsigned long long a0 = As2[k][ty * 4 + 0];
            unsigned long long a1 = As2[k][ty * 4 + 1];
            unsigned long long a2 = As2[k][ty * 4 + 2];
            unsigned long long a3 = As2[k][ty * 4 + 3];
            ulonglong2 bv = *(const ulonglong2*)&Bs[k][tx];
            FMA2(acc2[0][0], a0, bv.x); FMA2(acc2[0][1], a0, bv.y);
            FMA2(acc2[1][0], a1, bv.x); FMA2(acc2[1][1], a1, bv.y);
            FMA2(acc2[2][0], a2, bv.x); FMA2(acc2[2][1], a2, bv.y);
            FMA2(acc2[3][0], a3, bv.x); FMA2(acc2[3][1], a3, bv.y);
        }
        __syncthreads();
    }

#pragma unroll
    for (int r = 0; r < 4; r++) {
        ulonglong2 v; v.x = acc2[r][0]; v.y = acc2[r][1];
        *(ulonglong2*)&g_h[(blockRow + ty * 4 + r) * OUT_F + tx * 4] = v;
    }

    float4 a1v = *(const float4*)&a[tx * 4];
    float4 a2v = *(const float4*)&a[OUT_F + tx * 4];
#pragma unroll
    for (int r = 0; r < 4; r++) {
        float2 c01 = unpack2(acc2[r][0]);
        float2 c23 = unpack2(acc2[r][1]);
        float p1 = c01.x * a1v.x + c01.y * a1v.y + c23.x * a1v.z + c23.y * a1v.w;
        float p2 = c01.x * a2v.x + c01.y * a2v.y + c23.x * a2v.z + c23.y * a2v.w;
#pragma unroll
        for (int o = 16; o > 0; o >>= 1) {
            p1 += __shfl_xor_sync(0xffffffffu, p1, o);
            p2 += __shfl_xor_sync(0xffffffffu, p2, o);
        }
        if (tx == 0) {
            int row = blockRow + ty * 4 + r;
            g_s1[row] = p1;
            g_s2[row] = p2;
        }
    }
}

// ---------------- fused edge pass: es + direct bucket scatter ---------------
#define E_PER 4
__global__ __launch_bounds__(256) void edge_kernel(const float* __restrict__ ef,
                                                   const float* __restrict__ a,
                                                   const void* __restrict__ ei) {
    int t = blockIdx.x * blockDim.x + threadIdx.x;
    int base = t * E_PER;
    if (base >= N_EDGES) return;
    int is64 = g_is64;

    const float* a3 = a + 2 * OUT_F;
    float4 av0 = *(const float4*)&a3[0];
    float4 av1 = *(const float4*)&a3[4];
    float4 av2 = *(const float4*)&a3[8];
    float4 av3 = *(const float4*)&a3[12];

    float4 fv[E_PER][4];
#pragma unroll
    for (int j = 0; j < E_PER; j++) {
#pragma unroll
        for (int q = 0; q < 4; q++)
            fv[j][q] = *(const float4*)&ef[(base + j) * EDGE_D + q * 4];
    }
    int src[E_PER], dst[E_PER];
#pragma unroll
    for (int j = 0; j < E_PER; j++) {
        src[j] = load_idx(ei, 0, base + j, is64);
        dst[j] = load_idx(ei, 1, base + j, is64);
    }
#pragma unroll
    for (int j = 0; j < E_PER; j++) {
        float s = fv[j][0].x * av0.x + fv[j][0].y * av0.y + fv[j][0].z * av0.z + fv[j][0].w * av0.w
                + fv[j][1].x * av1.x + fv[j][1].y * av1.y + fv[j][1].z * av1.z + fv[j][1].w * av1.w
                + fv[j][2].x * av2.x + fv[j][2].y * av2.y + fv[j][2].z * av2.z + fv[j][2].w * av2.w
                + fv[j][3].x * av3.x + fv[j][3].y * av3.y + fv[j][3].z * av3.z + fv[j][3].w * av3.w;
        int pos = atomicAdd(&g_off[src[j]], 1);
        if (pos < CAP) {
            int slot = src[j] * CAP + pos;
            g_bdst[slot] = dst[j];
            g_beid[slot] = base + j;
            g_bes [slot] = s;
        }
    }
}

// ---------------- attention (block per row, measured best structure) --------
__global__ __launch_bounds__(128) void attn_kernel(float* __restrict__ out) {
    __shared__ int    sdst[CAP];
    __shared__ int    seid[CAP];
    __shared__ float  sw[CAP];
    __shared__ float  sinvz;
    __shared__ float4 racc[4][32];

    int i = blockIdx.x;
    int t = threadIdx.x;
    int g = t >> 5;                   // warp / edge-group
    int l = t & 31;                   // lane / feature chunk
    int d = g_off[i];
    if (d > CAP) d = CAP;

    if (d == 0) {                     // all-masked row -> uniform softmax = column mean
        float s = 0.f;
        for (int n = 0; n < N_NODES; n++) s += g_h[n * OUT_F + t];
        out[i * OUT_F + t] = s / (float)N_NODES;
        return;
    }

    float s1i = g_s1[i];
    if (t < d) {
        int slot = i * CAP + t;
        sdst[t] = g_bdst[slot];
        seid[t] = g_beid[slot];
        sw[t]   = g_bes [slot];
    }
    __syncthreads();

    if (t < d) {
        int dst = sdst[t];
        int eid = seid[t];
        // dedup duplicate (src,dst): last-written (max eid) edge wins.
        bool win = true;
        for (int k = 0; k < d; k++)
            if (sdst[k] == dst && seid[k] > eid) win = false;
        float e = -1e30f;
        if (win) {
            e = s1i + g_s2[dst] + sw[t];
            e = (e > 0.f) ? e : ALPHA * e;
        }
        sw[t] = e;
    }
    __syncthreads();

    // warp 0: row softmax (max, exp, sum) over d entries
    if (g == 0) {
        float v[4];
        float m = -1e30f;
#pragma unroll
        for (int j = 0; j < 4; j++) {
            int k = l + 32 * j;
            v[j] = (k < d) ? sw[k] : -1e30f;
            m = fmaxf(m, v[j]);
        }
#pragma unroll
        for (int o = 16; o > 0; o >>= 1) m = fmaxf(m, __shfl_xor_sync(0xffffffffu, m, o));
        float z = 0.f;
#pragma unroll
        for (int j = 0; j < 4; j++) {
            int k = l + 32 * j;
            if (k < d) {
                float w = __expf(v[j] - m);
                sw[k] = w;
                z += w;
            }
        }
#pragma unroll
        for (int o = 16; o > 0; o >>= 1) z += __shfl_xor_sync(0xffffffffu, z, o);
        if (l == 0) sinvz = 1.f / z;
    }
    __syncthreads();

    // gather: warp g handles edges g, g+4, ...; float4 per lane
    const float4* h4 = (const float4*)g_h;
    float4 acc = make_float4(0.f, 0.f, 0.f, 0.f);
    for (int k = g; k < d; k += 4) {
        float  wk  = sw[k];
        int    dst = sdst[k];
        float4 hv  = h4[dst * 32 + l];
        acc.x += wk * hv.x; acc.y += wk * hv.y; acc.z += wk * hv.z; acc.w += wk * hv.w;
    }
    racc[g][l] = acc;
    __syncthreads();

    if (g == 0) {
        float4 a0 = racc[0][l], a1 = racc[1][l], a2 = racc[2][l], a3 = racc[3][l];
        float invz = sinvz;
        float4 o;
        o.x = (a0.x + a1.x + a2.x + a3.x) * invz;
        o.y = (a0.y + a1.y + a2.y + a3.y) * invz;
        o.z = (a0.z + a1.z + a2.z + a3.z) * invz;
        o.w = (a0.w + a1.w + a2.w + a3.w) * invz;
        ((float4*)out)[i * 32 + l] = o;
    }
}

// ---------------- launch ----------------------------------------------------
extern "C" void kernel_launch(void* const* d_in, const int* in_sizes, int n_in,
                              void* d_out, int out_size) {
    const float* input_h       = (const float*)d_in[0];
    const void*  edge_index    = (const void*)d_in[1];
    const float* edge_features = (const float*)d_in[2];
    const float* W             = (const float*)d_in[3];
    const float* a             = (const float*)d_in[4];
    float* out = (float*)d_out;

    gemm_init_kernel<<<K1_BLOCKS, 256>>>(input_h, W, a, edge_index);
    edge_kernel<<<N_EDGES / (256 * E_PER), 256>>>(edge_features, a, edge_index);
    attn_kernel<<<N_NODES, 128>>>(out);
}

// round 16
// speedup vs baseline: 1.1196x; 1.0605x over previous
#include <cuda_runtime.h>
#include <math.h>

#define N_NODES 6144
#define N_EDGES 196608
#define IN_F    256
#define OUT_F   128
#define EDGE_D  16
#define ALPHA   0.2f
#define CAP     128          // per-row bucket capacity (Poisson(32) tail @128 ~ e^-85)

#define KSPLIT  2
#define GEMM_BLOCKS (N_NODES / 32 * KSPLIT)   // 384
#define COMB_BLOCKS (N_NODES / 8)             // 768 (8 rows per 256-thr block)
#define INIT_BLOCKS 24                        // 24 * 256 = 6144
#define K2_BLOCKS   (COMB_BLOCKS + INIT_BLOCKS)

// ---------------- scratch (static device globals; no allocation allowed) ----
__device__ float g_hp0[N_NODES * OUT_F];     // partial h, K-half 0
__device__ float g_hp1[N_NODES * OUT_F];     // partial h, K-half 1
__device__ float g_h  [N_NODES * OUT_F];     // transformed features
__device__ float g_s1[N_NODES];
__device__ float g_s2[N_NODES];
__device__ int   g_off[N_NODES];             // per-row fill count
__device__ int   g_bdst[N_NODES * CAP];      // bucket: dst node
__device__ int   g_beid[N_NODES * CAP];      // bucket: edge id (dedup tie-break)
__device__ float g_bes [N_NODES * CAP];      // bucket: edge score
__device__ int   g_is64 = 1;                 // dtype flag: only ever cleared

__device__ __forceinline__ int load_idx(const void* ei_raw, int row, int e, int is64) {
    int v;
    if (is64) v = (int)((const long long*)ei_raw)[(long long)row * N_EDGES + e];
    else      v = ((const int*)ei_raw)[row * N_EDGES + e];
    v = v < 0 ? 0 : (v >= N_NODES ? N_NODES - 1 : v);   // never form a wild address
    return v;
}

// ---------------- packed f32x2 helpers (sm_103a FFMA2) ----------------------
__device__ __forceinline__ unsigned long long pack2(float x) {
    unsigned long long r;
    asm("mov.b64 %0, {%1, %1};" : "=l"(r) : "f"(x));
    return r;
}
#define FMA2(d, a, b) asm("fma.rn.f32x2 %0, %1, %2, %0;" : "+l"(d) : "l"(a), "l"(b))

// ---------------- kernel 1: split-K SGEMM -----------------------------------
// 384 blocks: block b -> rows (b>>1)*32, K-half (b&1) of 128. Each half writes
// its own partial buffer (no atomics; combine kernel sums p0+p1 -> exact).
__global__ __launch_bounds__(256) void gemm_kernel(const float* __restrict__ A,
                                                   const float* __restrict__ B) {
    __shared__ unsigned long long As2[32][33];   // [k][m], value pre-packed {v,v}
    __shared__ float4 Bs[32][32];                // [k][col4]

    int tid = threadIdx.x;
    int ty  = tid >> 5;               // 0..7  -> rows ty*4 .. ty*4+3
    int tx  = tid & 31;               // 0..31 -> cols tx*4 .. tx*4+3
    int blockRow = (blockIdx.x >> 1) * 32;
    int kbase    = (blockIdx.x & 1) * (IN_F / KSPLIT);
    float* HP    = (blockIdx.x & 1) ? g_hp1 : g_hp0;

    int arow = tid >> 3;              // 0..31
    int ak4  = (tid & 7) * 4;         // 0,4,...,28

    unsigned long long acc2[4][2] = {};   // [row][pair]

    for (int k0 = kbase; k0 < kbase + IN_F / KSPLIT; k0 += 32) {
        float4 av = *(const float4*)&A[(blockRow + arow) * IN_F + k0 + ak4];
        As2[ak4 + 0][arow] = pack2(av.x);
        As2[ak4 + 1][arow] = pack2(av.y);
        As2[ak4 + 2][arow] = pack2(av.z);
        As2[ak4 + 3][arow] = pack2(av.w);
#pragma unroll
        for (int r = 0; r < 4; r++) {
            int idx = tid + r * 256;          // 0..1023
            int kb  = idx >> 5;               // 0..31
            int cb  = idx & 31;               // 0..31
            Bs[kb][cb] = *(const float4*)&B[(k0 + kb) * OUT_F + cb * 4];
        }
        __syncthreads();
#pragma unroll
        for (int k = 0; k < 32; k++) {
            unsigned long long a0 = As2[k][ty * 4 + 0];
            unsigned long long a1 = As2[k][ty * 4 + 1];
            unsigned long long a2 = As2[k][ty * 4 + 2];
            unsigned long long a3 = As2[k][ty * 4 + 3];
            ulonglong2 bv = *(const ulonglong2*)&Bs[k][tx];
            FMA2(acc2[0][0], a0, bv.x); FMA2(acc2[0][1], a0, bv.y);
            FMA2(acc2[1][0], a1, bv.x); FMA2(acc2[1][1], a1, bv.y);
            FMA2(acc2[2][0], a2, bv.x); FMA2(acc2[2][1], a2, bv.y);
            FMA2(acc2[3][0], a3, bv.x); FMA2(acc2[3][1], a3, bv.y);
        }
        __syncthreads();
    }

#pragma unroll
    for (int r = 0; r < 4; r++) {
        ulonglong2 v; v.x = acc2[r][0]; v.y = acc2[r][1];
        *(ulonglong2*)&HP[(blockRow + ty * 4 + r) * OUT_F + tx * 4] = v;
    }
}

// ---------------- kernel 2: combine halves + s1/s2 | init tail --------------
// Blocks [0,768): warp w -> row b*8+w; h = p0+p1 (order-fixed, exact), then
// s1 = h@a1, s2 = h@a2 via warp reduce. Blocks [768,792): g_off zero + probe.
__global__ __launch_bounds__(256) void combine_init_kernel(const float* __restrict__ a,
                                                           const void* __restrict__ ei_raw) {
    if (blockIdx.x >= COMB_BLOCKS) {
        int i = (blockIdx.x - COMB_BLOCKS) * 256 + threadIdx.x;   // 0..6143
        g_off[i] = 0;
        long long v = ((const long long*)ei_raw)[i];
        if (v < 0 || v >= N_NODES) g_is64 = 0;   // benign: only ever cleared
        return;
    }

    int w   = threadIdx.x >> 5;       // 0..7
    int l   = threadIdx.x & 31;       // chunk
    int row = blockIdx.x * 8 + w;

    const float4* p0 = (const float4*)g_hp0;
    const float4* p1 = (const float4*)g_hp1;
    float4 v0 = p0[row * 32 + l];
    float4 v1 = p1[row * 32 + l];
    float4 h  = make_float4(v0.x + v1.x, v0.y + v1.y, v0.z + v1.z, v0.w + v1.w);
    ((float4*)g_h)[row * 32 + l] = h;

    float4 a1v = *(const float4*)&a[l * 4];
    float4 a2v = *(const float4*)&a[OUT_F + l * 4];
    float p1d = h.x * a1v.x + h.y * a1v.y + h.z * a1v.z + h.w * a1v.w;
    float p2d = h.x * a2v.x + h.y * a2v.y + h.z * a2v.z + h.w * a2v.w;
#pragma unroll
    for (int o = 16; o > 0; o >>= 1) {
        p1d += __shfl_xor_sync(0xffffffffu, p1d, o);
        p2d += __shfl_xor_sync(0xffffffffu, p2d, o);
    }
    if (l == 0) { g_s1[row] = p1d; g_s2[row] = p2d; }
}

// ---------------- fused edge pass: es + direct bucket scatter ---------------
#define E_PER 4
__global__ __launch_bounds__(256) void edge_kernel(const float* __restrict__ ef,
                                                   const float* __restrict__ a,
                                                   const void* __restrict__ ei) {
    int t = blockIdx.x * blockDim.x + threadIdx.x;
    int base = t * E_PER;
    if (base >= N_EDGES) return;
    int is64 = g_is64;

    const float* a3 = a + 2 * OUT_F;
    float4 av0 = *(const float4*)&a3[0];
    float4 av1 = *(const float4*)&a3[4];
    float4 av2 = *(const float4*)&a3[8];
    float4 av3 = *(const float4*)&a3[12];

    float4 fv[E_PER][4];
#pragma unroll
    for (int j = 0; j < E_PER; j++) {
#pragma unroll
        for (int q = 0; q < 4; q++)
            fv[j][q] = *(const float4*)&ef[(base + j) * EDGE_D + q * 4];
    }
    int src[E_PER], dst[E_PER];
#pragma unroll
    for (int j = 0; j < E_PER; j++) {
        src[j] = load_idx(ei, 0, base + j, is64);
        dst[j] = load_idx(ei, 1, base + j, is64);
    }
#pragma unroll
    for (int j = 0; j < E_PER; j++) {
        float s = fv[j][0].x * av0.x + fv[j][0].y * av0.y + fv[j][0].z * av0.z + fv[j][0].w * av0.w
                + fv[j][1].x * av1.x + fv[j][1].y * av1.y + fv[j][1].z * av1.z + fv[j][1].w * av1.w
                + fv[j][2].x * av2.x + fv[j][2].y * av2.y + fv[j][2].z * av2.z + fv[j][2].w * av2.w
                + fv[j][3].x * av3.x + fv[j][3].y * av3.y + fv[j][3].z * av3.z + fv[j][3].w * av3.w;
        int pos = atomicAdd(&g_off[src[j]], 1);
        if (pos < CAP) {
            int slot = src[j] * CAP + pos;
            g_bdst[slot] = dst[j];
            g_beid[slot] = base + j;
            g_bes [slot] = s;
        }
    }
}

// ---------------- attention (block per row, measured best structure) --------
__global__ __launch_bounds__(128) void attn_kernel(float* __restrict__ out) {
    __shared__ int    sdst[CAP];
    __shared__ int    seid[CAP];
    __shared__ float  sw[CAP];
    __shared__ float  sinvz;
    __shared__ float4 racc[4][32];

    int i = blockIdx.x;
    int t = threadIdx.x;
    int g = t >> 5;                   // warp / edge-group
    int l = t & 31;                   // lane / feature chunk
    int d = g_off[i];
    if (d > CAP) d = CAP;

    if (d == 0) {                     // all-masked row -> uniform softmax = column mean
        float s = 0.f;
        for (int n = 0; n < N_NODES; n++) s += g_h[n * OUT_F + t];
        out[i * OUT_F + t] = s / (float)N_NODES;
        return;
    }

    float s1i = g_s1[i];
    if (t < d) {
        int slot = i * CAP + t;
        sdst[t] = g_bdst[slot];
        seid[t] = g_beid[slot];
        sw[t]   = g_bes [slot];
    }
    __syncthreads();

    if (t < d) {
        int dst = sdst[t];
        int eid = seid[t];
        // dedup duplicate (src,dst): last-written (max eid) edge wins.
        bool win = true;
        for (int k = 0; k < d; k++)
            if (sdst[k] == dst && seid[k] > eid) win = false;
        float e = -1e30f;
        if (win) {
            e = s1i + g_s2[dst] + sw[t];
            e = (e > 0.f) ? e : ALPHA * e;
        }
        sw[t] = e;
    }
    __syncthreads();

    // warp 0: row softmax (max, exp, sum) over d entries
    if (g == 0) {
        float v[4];
        float m = -1e30f;
#pragma unroll
        for (int j = 0; j < 4; j++) {
            int k = l + 32 * j;
            v[j] = (k < d) ? sw[k] : -1e30f;
            m = fmaxf(m, v[j]);
        }
#pragma unroll
        for (int o = 16; o > 0; o >>= 1) m = fmaxf(m, __shfl_xor_sync(0xffffffffu, m, o));
        float z = 0.f;
#pragma unroll
        for (int j = 0; j < 4; j++) {
            int k = l + 32 * j;
            if (k < d) {
                float w = __expf(v[j] - m);
                sw[k] = w;
                z += w;
            }
        }
#pragma unroll
        for (int o = 16; o > 0; o >>= 1) z += __shfl_xor_sync(0xffffffffu, z, o);
        if (l == 0) sinvz = 1.f / z;
    }
    __syncthreads();

    // gather: warp g handles edges g, g+4, ...; float4 per lane
    const float4* h4 = (const float4*)g_h;
    float4 acc = make_float4(0.f, 0.f, 0.f, 0.f);
    for (int k = g; k < d; k += 4) {
        float  wk  = sw[k];
        int    dst = sdst[k];
        float4 hv  = h4[dst * 32 + l];
        acc.x += wk * hv.x; acc.y += wk * hv.y; acc.z += wk * hv.z; acc.w += wk * hv.w;
    }
    racc[g][l] = acc;
    __syncthreads();

    if (g == 0) {
        float4 a0 = racc[0][l], a1 = racc[1][l], a2 = racc[2][l], a3 = racc[3][l];
        float invz = sinvz;
        float4 o;
        o.x = (a0.x + a1.x + a2.x + a3.x) * invz;
        o.y = (a0.y + a1.y + a2.y + a3.y) * invz;
        o.z = (a0.z + a1.z + a2.z + a3.z) * invz;
        o.w = (a0.w + a1.w + a2.w + a3.w) * invz;
        ((float4*)out)[i * 32 + l] = o;
    }
}

// ---------------- launch ----------------------------------------------------
extern "C" void kernel_launch(void* const* d_in, const int* in_sizes, int n_in,
                              void* d_out, int out_size) {
    const float* input_h       = (const float*)d_in[0];
    const void*  edge_index    = (const void*)d_in[1];
    const float* edge_features = (const float*)d_in[2];
    const float* W             = (const float*)d_in[3];
    const float* a             = (const float*)d_in[4];
    float* out = (float*)d_out;

    gemm_kernel<<<GEMM_BLOCKS, 256>>>(input_h, W);
    combine_init_kernel<<<K2_BLOCKS, 256>>>(a, edge_index);
    edge_kernel<<<N_EDGES / (256 * E_PER), 256>>>(edge_features, a, edge_index);
    attn_kernel<<<N_NODES, 128>>>(out);
}

// round 17
// speedup vs baseline: 1.1699x; 1.0449x over previous
#include <cuda_runtime.h>
#include <math.h>

#define N_NODES 6144
#define N_EDGES 196608
#define IN_F    256
#define OUT_F   128
#define EDGE_D  16
#define ALPHA   0.2f
#define CAP     128          // per-row bucket capacity (Poisson(32) tail @128 ~ e^-85)

#define KSPLIT  2
#define GEMM_BLOCKS (N_NODES / 32 * KSPLIT)   // 384
#define INIT_BLOCKS 24                        // 24 * 256 = 6144
#define K1_BLOCKS   (GEMM_BLOCKS + INIT_BLOCKS)

#define E_PER 4
#define EDGE_BLOCKS (N_EDGES / (256 * E_PER)) // 192
#define COMB_BLOCKS (N_NODES / 8)             // 768
#define K2_BLOCKS   (EDGE_BLOCKS + COMB_BLOCKS)

// ---------------- scratch (static device globals; no allocation allowed) ----
__device__ float g_hp0[N_NODES * OUT_F];     // partial h, K-half 0
__device__ float g_hp1[N_NODES * OUT_F];     // partial h, K-half 1
__device__ float g_h  [N_NODES * OUT_F];     // transformed features
__device__ float g_s1[N_NODES];
__device__ float g_s2[N_NODES];
__device__ int   g_off[N_NODES];             // per-row fill count
__device__ int   g_bdst[N_NODES * CAP];      // bucket: dst node
__device__ int   g_beid[N_NODES * CAP];      // bucket: edge id (dedup tie-break)
__device__ float g_bes [N_NODES * CAP];      // bucket: edge score
__device__ int   g_is64 = 1;                 // dtype flag: only ever cleared

__device__ __forceinline__ int load_idx(const void* ei_raw, int row, int e, int is64) {
    int v;
    if (is64) v = (int)((const long long*)ei_raw)[(long long)row * N_EDGES + e];
    else      v = ((const int*)ei_raw)[row * N_EDGES + e];
    v = v < 0 ? 0 : (v >= N_NODES ? N_NODES - 1 : v);   // never form a wild address
    return v;
}

// ---------------- packed f32x2 helpers (sm_103a FFMA2) ----------------------
__device__ __forceinline__ unsigned long long pack2(float x) {
    unsigned long long r;
    asm("mov.b64 %0, {%1, %1};" : "=l"(r) : "f"(x));
    return r;
}
#define FMA2(d, a, b) asm("fma.rn.f32x2 %0, %1, %2, %0;" : "+l"(d) : "l"(a), "l"(b))

// ---------------- kernel 1: split-K SGEMM | init tail -----------------------
// Blocks [0,384): block b -> rows (b>>1)*32, K-half (b&1). Partial buffers,
// no atomics. Blocks [384,408): zero g_off + dtype probe (used by kernel 2).
__global__ __launch_bounds__(256) void gemm_init_kernel(const float* __restrict__ A,
                                                        const float* __restrict__ B,
                                                        const void* __restrict__ ei_raw) {
    if (blockIdx.x >= GEMM_BLOCKS) {
        int i = (blockIdx.x - GEMM_BLOCKS) * 256 + threadIdx.x;   // 0..6143
        g_off[i] = 0;
        long long v = ((const long long*)ei_raw)[i];
        if (v < 0 || v >= N_NODES) g_is64 = 0;   // benign: only ever cleared
        return;
    }

    __shared__ unsigned long long As2[32][33];   // [k][m], value pre-packed {v,v}
    __shared__ float4 Bs[32][32];                // [k][col4]

    int tid = threadIdx.x;
    int ty  = tid >> 5;               // 0..7  -> rows ty*4 .. ty*4+3
    int tx  = tid & 31;               // 0..31 -> cols tx*4 .. tx*4+3
    int blockRow = (blockIdx.x >> 1) * 32;
    int kbase    = (blockIdx.x & 1) * (IN_F / KSPLIT);
    float* HP    = (blockIdx.x & 1) ? g_hp1 : g_hp0;

    int arow = tid >> 3;              // 0..31
    int ak4  = (tid & 7) * 4;         // 0,4,...,28

    unsigned long long acc2[4][2] = {};   // [row][pair]

    for (int k0 = kbase; k0 < kbase + IN_F / KSPLIT; k0 += 32) {
        float4 av = *(const float4*)&A[(blockRow + arow) * IN_F + k0 + ak4];
        As2[ak4 + 0][arow] = pack2(av.x);
        As2[ak4 + 1][arow] = pack2(av.y);
        As2[ak4 + 2][arow] = pack2(av.z);
        As2[ak4 + 3][arow] = pack2(av.w);
#pragma unroll
        for (int r = 0; r < 4; r++) {
            int idx = tid + r * 256;          // 0..1023
            int kb  = idx >> 5;               // 0..31
            int cb  = idx & 31;               // 0..31
            Bs[kb][cb] = *(const float4*)&B[(k0 + kb) * OUT_F + cb * 4];
        }
        __syncthreads();
#pragma unroll
        for (int k = 0; k < 32; k++) {
            unsigned long long a0 = As2[k][ty * 4 + 0];
            unsigned long long a1 = As2[k][ty * 4 + 1];
            unsigned long long a2 = As2[k][ty * 4 + 2];
            unsigned long long a3 = As2[k][ty * 4 + 3];
            ulonglong2 bv = *(const ulonglong2*)&Bs[k][tx];
            FMA2(acc2[0][0], a0, bv.x); FMA2(acc2[0][1], a0, bv.y);
            FMA2(acc2[1][0], a1, bv.x); FMA2(acc2[1][1], a1, bv.y);
            FMA2(acc2[2][0], a2, bv.x); FMA2(acc2[2][1], a2, bv.y);
            FMA2(acc2[3][0], a3, bv.x); FMA2(acc2[3][1], a3, bv.y);
        }
        __syncthreads();
    }

#pragma unroll
    for (int r = 0; r < 4; r++) {
        ulonglong2 v; v.x = acc2[r][0]; v.y = acc2[r][1];
        *(ulonglong2*)&HP[(blockRow + ty * 4 + r) * OUT_F + tx * 4] = v;
    }
}

// ---------------- kernel 2: edge pass | combine halves (fused launch) -------
// Blocks [0,192): per-edge es + bucket scatter. Blocks [192,960): h = p0+p1,
// s1/s2 warp-reduced dots. Independent work; mixed profiles fill the chip.
__global__ __launch_bounds__(256) void edge_combine_kernel(const float* __restrict__ ef,
                                                           const float* __restrict__ a,
                                                           const void* __restrict__ ei) {
    if (blockIdx.x >= EDGE_BLOCKS) {
        int b   = blockIdx.x - EDGE_BLOCKS;   // 0..767
        int w   = threadIdx.x >> 5;           // 0..7
        int l   = threadIdx.x & 31;
        int row = b * 8 + w;

        const float4* p0 = (const float4*)g_hp0;
        const float4* p1 = (const float4*)g_hp1;
        float4 v0 = p0[row * 32 + l];
        float4 v1 = p1[row * 32 + l];
        float4 h  = make_float4(v0.x + v1.x, v0.y + v1.y, v0.z + v1.z, v0.w + v1.w);
        ((float4*)g_h)[row * 32 + l] = h;

        float4 a1v = *(const float4*)&a[l * 4];
        float4 a2v = *(const float4*)&a[OUT_F + l * 4];
        float p1d = h.x * a1v.x + h.y * a1v.y + h.z * a1v.z + h.w * a1v.w;
        float p2d = h.x * a2v.x + h.y * a2v.y + h.z * a2v.z + h.w * a2v.w;
#pragma unroll
        for (int o = 16; o > 0; o >>= 1) {
            p1d += __shfl_xor_sync(0xffffffffu, p1d, o);
            p2d += __shfl_xor_sync(0xffffffffu, p2d, o);
        }
        if (l == 0) { g_s1[row] = p1d; g_s2[row] = p2d; }
        return;
    }

    int t = blockIdx.x * blockDim.x + threadIdx.x;
    int base = t * E_PER;
    int is64 = g_is64;

    const float* a3 = a + 2 * OUT_F;
    float4 av0 = *(const float4*)&a3[0];
    float4 av1 = *(const float4*)&a3[4];
    float4 av2 = *(const float4*)&a3[8];
    float4 av3 = *(const float4*)&a3[12];

    float4 fv[E_PER][4];
#pragma unroll
    for (int j = 0; j < E_PER; j++) {
#pragma unroll
        for (int q = 0; q < 4; q++)
            fv[j][q] = *(const float4*)&ef[(base + j) * EDGE_D + q * 4];
    }
    int src[E_PER], dst[E_PER];
#pragma unroll
    for (int j = 0; j < E_PER; j++) {
        src[j] = load_idx(ei, 0, base + j, is64);
        dst[j] = load_idx(ei, 1, base + j, is64);
    }
#pragma unroll
    for (int j = 0; j < E_PER; j++) {
        float s = fv[j][0].x * av0.x + fv[j][0].y * av0.y + fv[j][0].z * av0.z + fv[j][0].w * av0.w
                + fv[j][1].x * av1.x + fv[j][1].y * av1.y + fv[j][1].z * av1.z + fv[j][1].w * av1.w
                + fv[j][2].x * av2.x + fv[j][2].y * av2.y + fv[j][2].z * av2.z + fv[j][2].w * av2.w
                + fv[j][3].x * av3.x + fv[j][3].y * av3.y + fv[j][3].z * av3.z + fv[j][3].w * av3.w;
        int pos = atomicAdd(&g_off[src[j]], 1);
        if (pos < CAP) {
            int slot = src[j] * CAP + pos;
            g_bdst[slot] = dst[j];
            g_beid[slot] = base + j;
            g_bes [slot] = s;
        }
    }
}

// ---------------- attention (block per row; pipelined gather) ---------------
__global__ __launch_bounds__(128) void attn_kernel(float* __restrict__ out) {
    __shared__ int    sdst[CAP];
    __shared__ int    seid[CAP];
    __shared__ float  sw[CAP];
    __shared__ float  sinvz;
    __shared__ float4 racc[4][32];

    int i = blockIdx.x;
    int t = threadIdx.x;
    int g = t >> 5;                   // warp / edge-group
    int l = t & 31;                   // lane / feature chunk
    int d = g_off[i];
    if (d > CAP) d = CAP;

    if (d == 0) {                     // all-masked row -> uniform softmax = column mean
        float s = 0.f;
        for (int n = 0; n < N_NODES; n++) s += g_h[n * OUT_F + t];
        out[i * OUT_F + t] = s / (float)N_NODES;
        return;
    }

    float s1i = g_s1[i];
    if (t < d) {
        int slot = i * CAP + t;
        sdst[t] = g_bdst[slot];
        seid[t] = g_beid[slot];
        sw[t]   = g_bes [slot];
    }
    __syncthreads();

    if (t < d) {
        int dst = sdst[t];
        int eid = seid[t];
        // dedup duplicate (src,dst): last-written (max eid) edge wins.
        bool win = true;
        for (int k = 0; k < d; k++)
            if (sdst[k] == dst && seid[k] > eid) win = false;
        float e = -1e30f;
        if (win) {
            e = s1i + g_s2[dst] + sw[t];
            e = (e > 0.f) ? e : ALPHA * e;
        }
        sw[t] = e;
    }
    __syncthreads();

    // warp 0: row softmax (max, exp, sum) over d entries
    if (g == 0) {
        float v[4];
        float m = -1e30f;
#pragma unroll
        for (int j = 0; j < 4; j++) {
            int k = l + 32 * j;
            v[j] = (k < d) ? sw[k] : -1e30f;
            m = fmaxf(m, v[j]);
        }
#pragma unroll
        for (int o = 16; o > 0; o >>= 1) m = fmaxf(m, __shfl_xor_sync(0xffffffffu, m, o));
        float z = 0.f;
#pragma unroll
        for (int j = 0; j < 4; j++) {
            int k = l + 32 * j;
            if (k < d) {
                float w = __expf(v[j] - m);
                sw[k] = w;
                z += w;
            }
        }
#pragma unroll
        for (int o = 16; o > 0; o >>= 1) z += __shfl_xor_sync(0xffffffffu, z, o);
        if (l == 0) sinvz = 1.f / z;
    }
    __syncthreads();

    // gather: warp g handles edges g, g+4, ...; unroll-2 pipeline, 2 LDGs in flight
    const float4* h4 = (const float4*)g_h;
    float4 acc0 = make_float4(0.f, 0.f, 0.f, 0.f);
    float4 acc1 = make_float4(0.f, 0.f, 0.f, 0.f);
    int k = g;
    for (; k + 4 < d; k += 8) {
        float w0 = sw[k];     int d0 = sdst[k];
        float w1 = sw[k + 4]; int d1 = sdst[k + 4];
        float4 h0 = h4[d0 * 32 + l];
        float4 h1 = h4[d1 * 32 + l];
        acc0.x += w0 * h0.x; acc0.y += w0 * h0.y; acc0.z += w0 * h0.z; acc0.w += w0 * h0.w;
        acc1.x += w1 * h1.x; acc1.y += w1 * h1.y; acc1.z += w1 * h1.z; acc1.w += w1 * h1.w;
    }
    if (k < d) {
        float wk = sw[k]; int dk = sdst[k];
        float4 hv = h4[dk * 32 + l];
        acc0.x += wk * hv.x; acc0.y += wk * hv.y; acc0.z += wk * hv.z; acc0.w += wk * hv.w;
    }
    racc[g][l] = make_float4(acc0.x + acc1.x, acc0.y + acc1.y,
                             acc0.z + acc1.z, acc0.w + acc1.w);
    __syncthreads();

    if (g == 0) {
        float4 a0 = racc[0][l], a1 = racc[1][l], a2 = racc[2][l], a3 = racc[3][l];
        float invz = sinvz;
        float4 o;
        o.x = (a0.x + a1.x + a2.x + a3.x) * invz;
        o.y = (a0.y + a1.y + a2.y + a3.y) * invz;
        o.z = (a0.z + a1.z + a2.z + a3.z) * invz;
        o.w = (a0.w + a1.w + a2.w + a3.w) * invz;
        ((float4*)out)[i * 32 + l] = o;
    }
}

// ---------------- launch ----------------------------------------------------
extern "C" void kernel_launch(void* const* d_in, const int* in_sizes, int n_in,
                              void* d_out, int out_size) {
    const float* input_h       = (const float*)d_in[0];
    const void*  edge_index    = (const void*)d_in[1];
    const float* edge_features = (const float*)d_in[2];
    const float* W             = (const float*)d_in[3];
    const float* a             = (const float*)d_in[4];
    float* out = (float*)d_out;

    gemm_init_kernel<<<K1_BLOCKS, 256>>>(input_h, W, edge_index);
    edge_combine_kernel<<<K2_BLOCKS, 256>>>(edge_features, a, edge_index);
    attn_kernel<<<N_NODES, 128>>>(out);
}